// round 11
// baseline (speedup 1.0000x reference)
#include <cuda_runtime.h>
#include <math.h>

// Problem caps (N=100000, E=800000 per setup_inputs; small safety margin)
#define NCAP 100352
#define ECAP 802816
#define ETCAP (ECAP + NCAP)

// R11 = resubmission of R9/R10 (GPU acquisition timed out both times;
// kernel never ran). Hypothesis: exact fp32 scores via pre-contraction
// s = x@(W@a) + single-pass tf32 GEMMs.

// ---------------- device scratch (static, no allocation) ----------------
__device__ float g_h  [(size_t)NCAP * 128];   // per-layer transformed features
__device__ float g_x1 [(size_t)NCAP * 128];   // layer-1 output
__device__ float g_x2 [(size_t)NCAP * 128];   // layer-2 output
__device__ float g_agg[(size_t)NCAP * 512];   // layer-3 weighted x2 aggregate
__device__ float g_ss [NCAP * 4];             // s_src per node/head
__device__ float g_sd [NCAP * 4];             // s_dst per node/head
__device__ int   g_cnt [NCAP];
__device__ int   g_scan[NCAP];
__device__ int   g_bsum[1024];
__device__ int   g_off [NCAP + 1];
__device__ int   g_cur [NCAP];
__device__ int   g_csrc[ETCAP];
__device__ float g_wvs[3 * 512];              // per-layer W@a_src  [128,4]
__device__ float g_wvd[3 * 512];              // per-layer W@a_dst  [128,4]
__device__ int   g_i64;                       // 1 if edge_index is int64, 0 if int32

__device__ __forceinline__ float lrelu(float e) { return e > 0.f ? e : 0.2f * e; }

__device__ __forceinline__ int edge_at(const void* ei, int idx) {
    if (g_i64) return (int)((const long long*)ei)[idx];
    return ((const int*)ei)[idx];
}

// ---------------- edge dtype detection ----------------
__global__ void k_detect(const int* __restrict__ ei32, int nsamp) {
    __shared__ int any;
    if (threadIdx.x == 0) any = 0;
    __syncthreads();
    for (int i = threadIdx.x * 2 + 1; i < nsamp; i += 512)
        if (ei32[i] != 0) { any = 1; break; }
    __syncthreads();
    if (threadIdx.x == 0) g_i64 = any ? 0 : 1;
}

// ---------------- CSR build ----------------
__global__ void k_init_cnt(int N) {
    int i = blockIdx.x * blockDim.x + threadIdx.x;
    if (i < N) g_cnt[i] = 1;   // self loop
}

__global__ void k_hist(const void* __restrict__ ei, int E, int N) {
    int e = blockIdx.x * blockDim.x + threadIdx.x;
    if (e >= E) return;
    int dst = edge_at(ei, E + e);
    if ((unsigned)dst < (unsigned)N) atomicAdd(&g_cnt[dst], 1);
}

__global__ void k_scan1(int N) {
    __shared__ int sm[1024];
    int tid = threadIdx.x;
    int i = blockIdx.x * 1024 + tid;
    sm[tid] = (i < N) ? g_cnt[i] : 0;
    __syncthreads();
    for (int off = 1; off < 1024; off <<= 1) {
        int t = (tid >= off) ? sm[tid - off] : 0;
        __syncthreads();
        sm[tid] += t;
        __syncthreads();
    }
    if (i < N) g_scan[i] = sm[tid];
    if (tid == 1023) g_bsum[blockIdx.x] = sm[1023];
}

__global__ void k_scan2(int nb) {
    __shared__ int sm[1024];
    int tid = threadIdx.x;
    sm[tid] = (tid < nb) ? g_bsum[tid] : 0;
    __syncthreads();
    for (int off = 1; off < 1024; off <<= 1) {
        int t = (tid >= off) ? sm[tid - off] : 0;
        __syncthreads();
        sm[tid] += t;
        __syncthreads();
    }
    if (tid < nb) g_bsum[tid] = sm[tid];
}

__global__ void k_scan3(int N) {
    int i = blockIdx.x * 1024 + threadIdx.x;
    if (i >= N) return;
    int pre = (blockIdx.x > 0) ? g_bsum[blockIdx.x - 1] : 0;
    int inc = g_scan[i] + pre;
    g_off[i + 1] = inc;
    g_cur[i] = inc - g_cnt[i];
    if (i == 0) g_off[0] = 0;
}

__global__ void k_scatter(const void* __restrict__ ei, int E, int N) {
    int t = blockIdx.x * blockDim.x + threadIdx.x;
    int src, dst;
    if (t < E) {
        src = edge_at(ei, t);
        dst = edge_at(ei, E + t);
        if ((unsigned)src >= (unsigned)N || (unsigned)dst >= (unsigned)N) return;
    }
    else if (t < E + N) { src = dst = t - E; }
    else return;
    int pos = atomicAdd(&g_cur[dst], 1);
    g_csrc[pos] = src;
}

// ---------------- pre-contracted score vectors ----------------
// Layers 1/2 (C=32): wv[k][h] = sum_{c<32}  W[k,h*32+c]  * a[h,c]
// Layer  3  (C=128): wv[k][h] = sum_{f<128} W3[k,h*128+f]* a[h,f]
template <int L>   // 0,1 -> C=32 over W[128,128]; 2 -> C=128 over W3[128,512]
__global__ void k_wvec(const float* __restrict__ W, const float* __restrict__ as,
                       const float* __restrict__ ad)
{
    int t = blockIdx.x * blockDim.x + threadIdx.x;
    if (t >= 1024) return;
    int which = t >> 9;
    int idx = t & 511;
    int k = idx >> 2, hh = idx & 3;
    const float* a = which ? ad : as;
    float s = 0.f;
    if (L < 2) {
        const float* wr = W + (size_t)k * 128 + hh * 32;
        const float* ar = a + hh * 32;
        for (int c = 0; c < 32; c++) s += wr[c] * ar[c];
    } else {
        const float* wr = W + (size_t)k * 512 + hh * 128;
        const float* ar = a + hh * 128;
        for (int f = 0; f < 128; f++) s += wr[f] * ar[f];
    }
    (which ? g_wvd : g_wvs)[L * 512 + k * 4 + hh] = s;
}

// ---------------- scores: s[n,h] = X[n,:] @ wv[:,h] (exact fp32) ----------
// XSEL: 0 = external x, 1 = g_x1, 2 = g_x2.  L selects wv slot.
template <int XSEL, int L>
__global__ void k_scores(const float* __restrict__ Xext, int N)
{
    const float* X = (XSEL == 0) ? Xext : (XSEL == 1) ? (const float*)g_x1
                                                      : (const float*)g_x2;
    int warp = (blockIdx.x * blockDim.x + threadIdx.x) >> 5;
    if (warp >= N) return;
    int lane = threadIdx.x & 31;
    const float* xr = X + (size_t)warp * 128;
    const float* wvs = g_wvs + L * 512;
    const float* wvd = g_wvd + L * 512;
    float ps[4] = {0.f, 0.f, 0.f, 0.f}, pd[4] = {0.f, 0.f, 0.f, 0.f};
    #pragma unroll
    for (int kk = 0; kk < 4; kk++) {
        int k = kk * 32 + lane;
        float xv = xr[k];
        float4 vs = *(const float4*)&wvs[k * 4];
        float4 vd = *(const float4*)&wvd[k * 4];
        ps[0] += xv * vs.x; ps[1] += xv * vs.y; ps[2] += xv * vs.z; ps[3] += xv * vs.w;
        pd[0] += xv * vd.x; pd[1] += xv * vd.y; pd[2] += xv * vd.z; pd[3] += xv * vd.w;
    }
    #pragma unroll
    for (int o = 16; o > 0; o >>= 1)
        #pragma unroll
        for (int hh = 0; hh < 4; hh++) {
            ps[hh] += __shfl_xor_sync(0xffffffffu, ps[hh], o);
            pd[hh] += __shfl_xor_sync(0xffffffffu, pd[hh], o);
        }
    if (lane == 0) {
        *(float4*)&g_ss[warp * 4] = make_float4(ps[0], ps[1], ps[2], ps[3]);
        *(float4*)&g_sd[warp * 4] = make_float4(pd[0], pd[1], pd[2], pd[3]);
    }
}

// ---------------- TF32 tensor-core GEMM (single-pass) ----------------
__device__ __forceinline__ unsigned f2tf(float f) {
    unsigned u;
    asm("cvt.rna.tf32.f32 %0, %1;" : "=r"(u) : "f"(f));
    return u;
}
__device__ __forceinline__ uint4 cvt4(float4 v) {
    uint4 u;
    u.x = f2tf(v.x); u.y = f2tf(v.y); u.z = f2tf(v.z); u.w = f2tf(v.w);
    return u;
}
__device__ __forceinline__ void mma_tf32(float* d, const unsigned* a, const unsigned* b) {
    asm volatile(
        "mma.sync.aligned.m16n8k8.row.col.f32.tf32.tf32.f32 "
        "{%0,%1,%2,%3}, {%4,%5,%6,%7}, {%8,%9}, {%0,%1,%2,%3};\n"
        : "+f"(d[0]), "+f"(d[1]), "+f"(d[2]), "+f"(d[3])
        : "r"(a[0]), "r"(a[1]), "r"(a[2]), "r"(a[3]), "r"(b[0]), "r"(b[1]));
}

#define AS_STRIDE 20
#define BS_STRIDE 136

// BM=128, BN=128, BK=16, 256 threads, 8 warps; warp tile 32x64 (m16n8k8).
// MODE 0: C = A@B into g_h (B is [K,128] row-major), ASEL 0 = ext, 1 = g_x1.
// MODE 1: layer-3 (A = g_agg, K=512): B row j = W3[(j%128), (j/128)*128+:],
//         Cext = 0.25*acc + bias + g_x2.
template <int KDIM, int MODE, int ASEL>
__global__ void __launch_bounds__(256, 2)
k_mma(const float* __restrict__ Aext, const float* __restrict__ B,
      float* __restrict__ Cext, const float* __restrict__ bias, int M)
{
    const float* A = (ASEL == 0) ? Aext : (ASEL == 1) ? (const float*)g_x1
                                                      : (const float*)g_agg;
    __shared__ unsigned As[128 * AS_STRIDE];
    __shared__ unsigned Bs[16 * BS_STRIDE];

    const int tid = threadIdx.x;
    const int lane = tid & 31;
    const int wid = tid >> 5;
    const int warpM = wid >> 1, warpN = wid & 1;
    const int rowBase = blockIdx.x * 128;

    const int aRow = tid >> 2;
    const int aCol = (tid & 3) * 4;
    const int bRow = tid >> 4;
    const int bCol = (tid & 15) * 4;

    float acc[2][8][4];
    #pragma unroll
    for (int t = 0; t < 2; t++)
        #pragma unroll
        for (int j = 0; j < 8; j++)
            #pragma unroll
            for (int q = 0; q < 4; q++) acc[t][j][q] = 0.f;

    const float4 z4 = make_float4(0.f, 0.f, 0.f, 0.f);
    float4 pa0, pa1, pb0, pb1;

    {   // prefetch k0 = 0
        int r0 = rowBase + aRow;
        pa0 = (r0 < M) ? *(const float4*)&A[(size_t)r0 * KDIM + aCol] : z4;
        int r1 = r0 + 64;
        pa1 = (r1 < M) ? *(const float4*)&A[(size_t)r1 * KDIM + aCol] : z4;
        int j = bRow;
        const float* br = (MODE == 1) ? B + (size_t)(j & 127) * 512 + (size_t)(j >> 7) * 128
                                      : B + (size_t)j * 128;
        pb0 = *(const float4*)&br[bCol];
        pb1 = *(const float4*)&br[bCol + 64];
    }

    for (int k0 = 0; k0 < KDIM; k0 += 16) {
        *(uint4*)&As[aRow * AS_STRIDE + aCol]        = cvt4(pa0);
        *(uint4*)&As[(aRow + 64) * AS_STRIDE + aCol] = cvt4(pa1);
        *(uint4*)&Bs[bRow * BS_STRIDE + bCol]        = cvt4(pb0);
        *(uint4*)&Bs[bRow * BS_STRIDE + bCol + 64]   = cvt4(pb1);
        __syncthreads();

        if (k0 + 16 < KDIM) {
            int kn = k0 + 16;
            int r0 = rowBase + aRow;
            pa0 = (r0 < M) ? *(const float4*)&A[(size_t)r0 * KDIM + kn + aCol] : z4;
            int r1 = r0 + 64;
            pa1 = (r1 < M) ? *(const float4*)&A[(size_t)r1 * KDIM + kn + aCol] : z4;
            int j = kn + bRow;
            const float* br = (MODE == 1) ? B + (size_t)(j & 127) * 512 + (size_t)(j >> 7) * 128
                                          : B + (size_t)j * 128;
            pb0 = *(const float4*)&br[bCol];
            pb1 = *(const float4*)&br[bCol + 64];
        }

        #pragma unroll
        for (int s = 0; s < 2; s++) {
            const int kc = s * 8;
            unsigned af[2][4];
            const int arow = warpM * 32 + (lane >> 2);
            const int acol = kc + (lane & 3);
            #pragma unroll
            for (int t = 0; t < 2; t++) {
                int r = arow + t * 16;
                af[t][0] = As[r * AS_STRIDE + acol];
                af[t][1] = As[(r + 8) * AS_STRIDE + acol];
                af[t][2] = As[r * AS_STRIDE + acol + 4];
                af[t][3] = As[(r + 8) * AS_STRIDE + acol + 4];
            }
            const int bk = kc + (lane & 3);
            #pragma unroll
            for (int j = 0; j < 8; j++) {
                int bn = warpN * 64 + j * 8 + (lane >> 2);
                unsigned bf[2];
                bf[0] = Bs[bk * BS_STRIDE + bn];
                bf[1] = Bs[(bk + 4) * BS_STRIDE + bn];
                #pragma unroll
                for (int t = 0; t < 2; t++)
                    mma_tf32(acc[t][j], af[t], bf);
            }
        }
        __syncthreads();
    }

    #pragma unroll
    for (int t = 0; t < 2; t++) {
        int r0 = rowBase + warpM * 32 + t * 16 + (lane >> 2);
        int r1 = r0 + 8;
        #pragma unroll
        for (int j = 0; j < 8; j++) {
            int c = warpN * 64 + j * 8 + 2 * (lane & 3);
            if (MODE == 0) {
                *(float2*)&g_h[(size_t)r0 * 128 + c] = make_float2(acc[t][j][0], acc[t][j][1]);
                *(float2*)&g_h[(size_t)r1 * 128 + c] = make_float2(acc[t][j][2], acc[t][j][3]);
            } else {
                if (r0 < M) {
                    float v0 = 0.25f * acc[t][j][0] + bias[c]     + g_x2[(size_t)r0 * 128 + c];
                    float v1 = 0.25f * acc[t][j][1] + bias[c + 1] + g_x2[(size_t)r0 * 128 + c + 1];
                    *(float2*)&Cext[(size_t)r0 * 128 + c] = make_float2(v0, v1);
                }
                if (r1 < M) {
                    float v2 = 0.25f * acc[t][j][2] + bias[c]     + g_x2[(size_t)r1 * 128 + c];
                    float v3 = 0.25f * acc[t][j][3] + bias[c + 1] + g_x2[(size_t)r1 * 128 + c + 1];
                    *(float2*)&Cext[(size_t)r1 * 128 + c] = make_float2(v2, v3);
                }
            }
        }
    }
}

// ---------------- per-node softmax + aggregate (layers 1/2) -----------------
template <int LAYER>
__global__ void k_agg(const float* __restrict__ xext,
                      const float* __restrict__ bias, int N)
{
    const float* xin = (LAYER == 1) ? xext : (const float*)g_x1;
    float* xout = (LAYER == 1) ? (float*)g_x1 : (float*)g_x2;

    int warp = (blockIdx.x * blockDim.x + threadIdx.x) >> 5;
    if (warp >= N) return;
    int lane = threadIdx.x & 31;
    int beg = g_off[warp], end = g_off[warp + 1];
    int deg = end - beg;

    float4 sdv = *(const float4*)(g_sd + 4 * warp);
    float e0 = -1e30f, e1 = -1e30f, e2 = -1e30f, e3 = -1e30f;
    int sl = 0;
    if (lane < deg) {
        sl = g_csrc[beg + lane];
        float4 sv = *(const float4*)(g_ss + 4 * sl);
        e0 = lrelu(sv.x + sdv.x); e1 = lrelu(sv.y + sdv.y);
        e2 = lrelu(sv.z + sdv.z); e3 = lrelu(sv.w + sdv.w);
    }
    float m0 = e0, m1 = e1, m2 = e2, m3 = e3;
    for (int i = beg + 32 + lane; i < end; i += 32) {
        int s = g_csrc[i];
        float4 sv = *(const float4*)(g_ss + 4 * s);
        m0 = fmaxf(m0, lrelu(sv.x + sdv.x)); m1 = fmaxf(m1, lrelu(sv.y + sdv.y));
        m2 = fmaxf(m2, lrelu(sv.z + sdv.z)); m3 = fmaxf(m3, lrelu(sv.w + sdv.w));
    }
    #pragma unroll
    for (int o = 16; o > 0; o >>= 1) {
        m0 = fmaxf(m0, __shfl_xor_sync(0xffffffffu, m0, o));
        m1 = fmaxf(m1, __shfl_xor_sync(0xffffffffu, m1, o));
        m2 = fmaxf(m2, __shfl_xor_sync(0xffffffffu, m2, o));
        m3 = fmaxf(m3, __shfl_xor_sync(0xffffffffu, m3, o));
    }

    int hsel = lane >> 3;
    float4 vacc = make_float4(0.f, 0.f, 0.f, 0.f);
    float z0 = 0.f, z1 = 0.f, z2 = 0.f, z3 = 0.f;
    int nf = deg < 32 ? deg : 32;
    for (int i = 0; i < nf; i++) {
        float q0 = __shfl_sync(0xffffffffu, e0, i);
        float q1 = __shfl_sync(0xffffffffu, e1, i);
        float q2 = __shfl_sync(0xffffffffu, e2, i);
        float q3 = __shfl_sync(0xffffffffu, e3, i);
        int s = __shfl_sync(0xffffffffu, sl, i);
        float p0 = __expf(q0 - m0), p1 = __expf(q1 - m1);
        float p2 = __expf(q2 - m2), p3 = __expf(q3 - m3);
        z0 += p0; z1 += p1; z2 += p2; z3 += p3;
        float ph = (hsel == 0) ? p0 : (hsel == 1) ? p1 : (hsel == 2) ? p2 : p3;
        float4 row = *(const float4*)&g_h[(size_t)s * 128 + 4 * lane];
        vacc.x += ph * row.x; vacc.y += ph * row.y;
        vacc.z += ph * row.z; vacc.w += ph * row.w;
    }
    for (int i = beg + 32; i < end; i++) {
        int s = g_csrc[i];
        float4 sv = *(const float4*)(g_ss + 4 * s);
        float p0 = __expf(lrelu(sv.x + sdv.x) - m0), p1 = __expf(lrelu(sv.y + sdv.y) - m1);
        float p2 = __expf(lrelu(sv.z + sdv.z) - m2), p3 = __expf(lrelu(sv.w + sdv.w) - m3);
        z0 += p0; z1 += p1; z2 += p2; z3 += p3;
        float ph = (hsel == 0) ? p0 : (hsel == 1) ? p1 : (hsel == 2) ? p2 : p3;
        float4 row = *(const float4*)&g_h[(size_t)s * 128 + 4 * lane];
        vacc.x += ph * row.x; vacc.y += ph * row.y;
        vacc.z += ph * row.z; vacc.w += ph * row.w;
    }

    float zh = (hsel == 0) ? z0 : (hsel == 1) ? z1 : (hsel == 2) ? z2 : z3;
    float inv = 1.f / (zh + 1e-16f);
    int f = 4 * lane;
    float4 bi = *(const float4*)&bias[f];
    float4 xi = *(const float4*)&xin[(size_t)warp * 128 + f];
    float4 v;
    v.x = vacc.x * inv + bi.x + xi.x;  v.x = v.x > 0.f ? v.x : expm1f(v.x);
    v.y = vacc.y * inv + bi.y + xi.y;  v.y = v.y > 0.f ? v.y : expm1f(v.y);
    v.z = vacc.z * inv + bi.z + xi.z;  v.z = v.z > 0.f ? v.z : expm1f(v.z);
    v.w = vacc.w * inv + bi.w + xi.w;  v.w = v.w > 0.f ? v.w : expm1f(v.w);
    *(float4*)&xout[(size_t)warp * 128 + f] = v;
}

// ---------------- layer-3 aggregate: agg[n,h*128+k] = sum_e alpha_h x2[src,k]
__global__ void k_agg3(int N)
{
    int warp = (blockIdx.x * blockDim.x + threadIdx.x) >> 5;
    if (warp >= N) return;
    int lane = threadIdx.x & 31;
    int beg = g_off[warp], end = g_off[warp + 1];
    int deg = end - beg;

    float4 sdv = *(const float4*)(g_sd + 4 * warp);
    float e0 = -1e30f, e1 = -1e30f, e2 = -1e30f, e3 = -1e30f;
    int sl = 0;
    if (lane < deg) {
        sl = g_csrc[beg + lane];
        float4 sv = *(const float4*)(g_ss + 4 * sl);
        e0 = lrelu(sv.x + sdv.x); e1 = lrelu(sv.y + sdv.y);
        e2 = lrelu(sv.z + sdv.z); e3 = lrelu(sv.w + sdv.w);
    }
    float m0 = e0, m1 = e1, m2 = e2, m3 = e3;
    for (int i = beg + 32 + lane; i < end; i += 32) {
        int s = g_csrc[i];
        float4 sv = *(const float4*)(g_ss + 4 * s);
        m0 = fmaxf(m0, lrelu(sv.x + sdv.x)); m1 = fmaxf(m1, lrelu(sv.y + sdv.y));
        m2 = fmaxf(m2, lrelu(sv.z + sdv.z)); m3 = fmaxf(m3, lrelu(sv.w + sdv.w));
    }
    #pragma unroll
    for (int o = 16; o > 0; o >>= 1) {
        m0 = fmaxf(m0, __shfl_xor_sync(0xffffffffu, m0, o));
        m1 = fmaxf(m1, __shfl_xor_sync(0xffffffffu, m1, o));
        m2 = fmaxf(m2, __shfl_xor_sync(0xffffffffu, m2, o));
        m3 = fmaxf(m3, __shfl_xor_sync(0xffffffffu, m3, o));
    }

    float4 va0 = make_float4(0,0,0,0), va1 = va0, va2 = va0, va3 = va0;
    float z0 = 0.f, z1 = 0.f, z2 = 0.f, z3 = 0.f;
    int nf = deg < 32 ? deg : 32;
    for (int i = 0; i < nf; i++) {
        float q0 = __shfl_sync(0xffffffffu, e0, i);
        float q1 = __shfl_sync(0xffffffffu, e1, i);
        float q2 = __shfl_sync(0xffffffffu, e2, i);
        float q3 = __shfl_sync(0xffffffffu, e3, i);
        int s = __shfl_sync(0xffffffffu, sl, i);
        float p0 = __expf(q0 - m0), p1 = __expf(q1 - m1);
        float p2 = __expf(q2 - m2), p3 = __expf(q3 - m3);
        z0 += p0; z1 += p1; z2 += p2; z3 += p3;
        float4 row = *(const float4*)&g_x2[(size_t)s * 128 + 4 * lane];
        va0.x += p0*row.x; va0.y += p0*row.y; va0.z += p0*row.z; va0.w += p0*row.w;
        va1.x += p1*row.x; va1.y += p1*row.y; va1.z += p1*row.z; va1.w += p1*row.w;
        va2.x += p2*row.x; va2.y += p2*row.y; va2.z += p2*row.z; va2.w += p2*row.w;
        va3.x += p3*row.x; va3.y += p3*row.y; va3.z += p3*row.z; va3.w += p3*row.w;
    }
    for (int i = beg + 32; i < end; i++) {
        int s = g_csrc[i];
        float4 sv = *(const float4*)(g_ss + 4 * s);
        float p0 = __expf(lrelu(sv.x + sdv.x) - m0), p1 = __expf(lrelu(sv.y + sdv.y) - m1);
        float p2 = __expf(lrelu(sv.z + sdv.z) - m2), p3 = __expf(lrelu(sv.w + sdv.w) - m3);
        z0 += p0; z1 += p1; z2 += p2; z3 += p3;
        float4 row = *(const float4*)&g_x2[(size_t)s * 128 + 4 * lane];
        va0.x += p0*row.x; va0.y += p0*row.y; va0.z += p0*row.z; va0.w += p0*row.w;
        va1.x += p1*row.x; va1.y += p1*row.y; va1.z += p1*row.z; va1.w += p1*row.w;
        va2.x += p2*row.x; va2.y += p2*row.y; va2.z += p2*row.z; va2.w += p2*row.w;
        va3.x += p3*row.x; va3.y += p3*row.y; va3.z += p3*row.z; va3.w += p3*row.w;
    }

    float i0 = 1.f/(z0+1e-16f), i1 = 1.f/(z1+1e-16f), i2 = 1.f/(z2+1e-16f), i3 = 1.f/(z3+1e-16f);
    size_t base = (size_t)warp * 512 + 4 * lane;
    *(float4*)&g_agg[base]       = make_float4(va0.x*i0, va0.y*i0, va0.z*i0, va0.w*i0);
    *(float4*)&g_agg[base + 128] = make_float4(va1.x*i1, va1.y*i1, va1.z*i1, va1.w*i1);
    *(float4*)&g_agg[base + 256] = make_float4(va2.x*i2, va2.y*i2, va2.z*i2, va2.w*i2);
    *(float4*)&g_agg[base + 384] = make_float4(va3.x*i3, va3.y*i3, va3.z*i3, va3.w*i3);
}

// ---------------- host entry ----------------
extern "C" void kernel_launch(void* const* d_in, const int* in_sizes, int n_in,
                              void* d_out, int out_size)
{
    const float* x   = (const float*)d_in[0];
    const void*  ei  = d_in[1];
    const float* W1  = (const float*)d_in[2];
    const float* as1 = (const float*)d_in[3];
    const float* ad1 = (const float*)d_in[4];
    const float* b1  = (const float*)d_in[5];
    const float* W2  = (const float*)d_in[6];
    const float* as2 = (const float*)d_in[7];
    const float* ad2 = (const float*)d_in[8];
    const float* b2  = (const float*)d_in[9];
    const float* W3  = (const float*)d_in[10];
    const float* as3 = (const float*)d_in[11];
    const float* ad3 = (const float*)d_in[12];
    const float* b3  = (const float*)d_in[13];

    int N = in_sizes[0] / 128;
    int E = in_sizes[1] / 2;

    int nb = (N + 1023) / 1024;
    int nsamp = (2 * E < 8192) ? 2 * E : 8192;

    // edge dtype detect + CSR build + score-vector precompute
    k_detect<<<1, 512>>>((const int*)ei, nsamp);
    k_init_cnt<<<nb, 1024>>>(N);
    k_hist<<<(E + 255) / 256, 256>>>(ei, E, N);
    k_wvec<0><<<4, 256>>>(W1, as1, ad1);
    k_wvec<1><<<4, 256>>>(W2, as2, ad2);
    k_wvec<2><<<4, 256>>>(W3, as3, ad3);
    k_scan1<<<nb, 1024>>>(N);
    k_scan2<<<1, 1024>>>(nb);
    k_scan3<<<nb, 1024>>>(N);
    k_scatter<<<(E + N + 255) / 256, 256>>>(ei, E, N);

    int gemmBlocks = (N + 127) / 128;
    int aggBlocks  = (N + 7) / 8;   // 8 warps (nodes) per 256-thread block

    // layer 1: exact fp32 scores from x; single-tf32 GEMM for h
    k_scores<0, 0><<<aggBlocks, 256>>>(x, N);
    k_mma<128, 0, 0><<<gemmBlocks, 256>>>(x, W1, nullptr, nullptr, N);
    k_agg<1><<<aggBlocks, 256>>>(x, b1, N);

    // layer 2
    k_scores<1, 1><<<aggBlocks, 256>>>(nullptr, N);
    k_mma<128, 0, 1><<<gemmBlocks, 256>>>(nullptr, W2, nullptr, nullptr, N);
    k_agg<2><<<aggBlocks, 256>>>(nullptr, b2, N);

    // layer 3 (never materializes h3 = [N,4,128])
    k_scores<2, 2><<<aggBlocks, 256>>>(nullptr, N);
    k_agg3<<<aggBlocks, 256>>>(N);
    k_mma<512, 1, 2><<<gemmBlocks, 256>>>(nullptr, W3, (float*)d_out, b3, N);
}

// round 12
// speedup vs baseline: 1.4879x; 1.4879x over previous
#include <cuda_runtime.h>
#include <math.h>

// Problem caps (N=100000, E=800000 per setup_inputs; small safety margin)
#define NCAP 100352
#define ECAP 802816
#define ETCAP (ECAP + NCAP)

// ---------------- device scratch (static, no allocation) ----------------
__device__ float g_h  [(size_t)NCAP * 128];   // per-layer transformed features
__device__ float g_x1 [(size_t)NCAP * 128];   // layer-1 output
__device__ float g_x2 [(size_t)NCAP * 128];   // layer-2 output
__device__ float g_agg[(size_t)NCAP * 512];   // layer-3 weighted x2 aggregate
__device__ float g_ss [2 * NCAP * 4];         // s_src, double-buffered (A=0, B=1)
__device__ float g_sd [2 * NCAP * 4];         // s_dst, double-buffered
__device__ int   g_cnt [NCAP];
__device__ int   g_scan[NCAP];
__device__ int   g_bsum[1024];
__device__ int   g_off [NCAP + 1];
__device__ int   g_cur [NCAP];
__device__ int   g_csrc[ETCAP];
__device__ float g_wvs[3 * 512];              // per-layer W@a_src  [128,4]
__device__ float g_wvd[3 * 512];              // per-layer W@a_dst  [128,4]
__device__ int   g_i64;                       // 1 if edge_index is int64, 0 if int32

__device__ __forceinline__ float lrelu(float e) { return e > 0.f ? e : 0.2f * e; }

__device__ __forceinline__ int edge_at(const void* ei, int idx) {
    if (g_i64) return (int)((const long long*)ei)[idx];
    return ((const int*)ei)[idx];
}

// ---------------- edge dtype detection ----------------
__global__ void k_detect(const int* __restrict__ ei32, int nsamp) {
    __shared__ int any;
    if (threadIdx.x == 0) any = 0;
    __syncthreads();
    for (int i = threadIdx.x * 2 + 1; i < nsamp; i += 512)
        if (ei32[i] != 0) { any = 1; break; }
    __syncthreads();
    if (threadIdx.x == 0) g_i64 = any ? 0 : 1;
}

// ---------------- CSR build ----------------
__global__ void k_init_cnt(int N) {
    int i = blockIdx.x * blockDim.x + threadIdx.x;
    if (i < N) g_cnt[i] = 1;   // self loop
}

__global__ void k_hist(const void* __restrict__ ei, int E, int N) {
    int e = blockIdx.x * blockDim.x + threadIdx.x;
    if (e >= E) return;
    int dst = edge_at(ei, E + e);
    if ((unsigned)dst < (unsigned)N) atomicAdd(&g_cnt[dst], 1);
}

__global__ void k_scan1(int N) {
    __shared__ int sm[1024];
    int tid = threadIdx.x;
    int i = blockIdx.x * 1024 + tid;
    sm[tid] = (i < N) ? g_cnt[i] : 0;
    __syncthreads();
    for (int off = 1; off < 1024; off <<= 1) {
        int t = (tid >= off) ? sm[tid - off] : 0;
        __syncthreads();
        sm[tid] += t;
        __syncthreads();
    }
    if (i < N) g_scan[i] = sm[tid];
    if (tid == 1023) g_bsum[blockIdx.x] = sm[1023];
}

__global__ void k_scan2(int nb) {
    __shared__ int sm[1024];
    int tid = threadIdx.x;
    sm[tid] = (tid < nb) ? g_bsum[tid] : 0;
    __syncthreads();
    for (int off = 1; off < 1024; off <<= 1) {
        int t = (tid >= off) ? sm[tid - off] : 0;
        __syncthreads();
        sm[tid] += t;
        __syncthreads();
    }
    if (tid < nb) g_bsum[tid] = sm[tid];
}

__global__ void k_scan3(int N) {
    int i = blockIdx.x * 1024 + threadIdx.x;
    if (i >= N) return;
    int pre = (blockIdx.x > 0) ? g_bsum[blockIdx.x - 1] : 0;
    int inc = g_scan[i] + pre;
    g_off[i + 1] = inc;
    g_cur[i] = inc - g_cnt[i];
    if (i == 0) g_off[0] = 0;
}

__global__ void k_scatter(const void* __restrict__ ei, int E, int N) {
    int t = blockIdx.x * blockDim.x + threadIdx.x;
    int src, dst;
    if (t < E) {
        src = edge_at(ei, t);
        dst = edge_at(ei, E + t);
        if ((unsigned)src >= (unsigned)N || (unsigned)dst >= (unsigned)N) return;
    }
    else if (t < E + N) { src = dst = t - E; }
    else return;
    int pos = atomicAdd(&g_cur[dst], 1);
    g_csrc[pos] = src;
}

// ---------------- pre-contracted score vectors ----------------
// Layers 1/2 (C=32): wv[k][h] = sum_{c<32}  W[k,h*32+c]  * a[h,c]
// Layer  3  (C=128): wv[k][h] = sum_{f<128} W3[k,h*128+f]* a[h,f]
template <int L>
__global__ void k_wvec(const float* __restrict__ W, const float* __restrict__ as,
                       const float* __restrict__ ad)
{
    int t = blockIdx.x * blockDim.x + threadIdx.x;
    if (t >= 1024) return;
    int which = t >> 9;
    int idx = t & 511;
    int k = idx >> 2, hh = idx & 3;
    const float* a = which ? ad : as;
    float s = 0.f;
    if (L < 2) {
        const float* wr = W + (size_t)k * 128 + hh * 32;
        const float* ar = a + hh * 32;
        for (int c = 0; c < 32; c++) s += wr[c] * ar[c];
    } else {
        const float* wr = W + (size_t)k * 512 + hh * 128;
        const float* ar = a + hh * 128;
        for (int f = 0; f < 128; f++) s += wr[f] * ar[f];
    }
    (which ? g_wvd : g_wvs)[L * 512 + k * 4 + hh] = s;
}

// ---------------- layer-1 scores from x (exact fp32) -> buffer A ----------
__global__ void k_scores1(const float* __restrict__ X, int N)
{
    int warp = (blockIdx.x * blockDim.x + threadIdx.x) >> 5;
    if (warp >= N) return;
    int lane = threadIdx.x & 31;
    const float* xr = X + (size_t)warp * 128;
    const float* wvs = g_wvs;      // slot 0
    const float* wvd = g_wvd;
    float ps[4] = {0.f, 0.f, 0.f, 0.f}, pd[4] = {0.f, 0.f, 0.f, 0.f};
    #pragma unroll
    for (int kk = 0; kk < 4; kk++) {
        int k = kk * 32 + lane;
        float xv = xr[k];
        float4 vs = *(const float4*)&wvs[k * 4];
        float4 vd = *(const float4*)&wvd[k * 4];
        ps[0] += xv * vs.x; ps[1] += xv * vs.y; ps[2] += xv * vs.z; ps[3] += xv * vs.w;
        pd[0] += xv * vd.x; pd[1] += xv * vd.y; pd[2] += xv * vd.z; pd[3] += xv * vd.w;
    }
    #pragma unroll
    for (int o = 16; o > 0; o >>= 1)
        #pragma unroll
        for (int hh = 0; hh < 4; hh++) {
            ps[hh] += __shfl_xor_sync(0xffffffffu, ps[hh], o);
            pd[hh] += __shfl_xor_sync(0xffffffffu, pd[hh], o);
        }
    if (lane == 0) {
        *(float4*)&g_ss[warp * 4] = make_float4(ps[0], ps[1], ps[2], ps[3]);
        *(float4*)&g_sd[warp * 4] = make_float4(pd[0], pd[1], pd[2], pd[3]);
    }
}

// ---------------- TF32 tensor-core GEMM (single-pass) ----------------
__device__ __forceinline__ unsigned f2tf(float f) {
    unsigned u;
    asm("cvt.rna.tf32.f32 %0, %1;" : "=r"(u) : "f"(f));
    return u;
}
__device__ __forceinline__ uint4 cvt4(float4 v) {
    uint4 u;
    u.x = f2tf(v.x); u.y = f2tf(v.y); u.z = f2tf(v.z); u.w = f2tf(v.w);
    return u;
}
__device__ __forceinline__ void mma_tf32(float* d, const unsigned* a, const unsigned* b) {
    asm volatile(
        "mma.sync.aligned.m16n8k8.row.col.f32.tf32.tf32.f32 "
        "{%0,%1,%2,%3}, {%4,%5,%6,%7}, {%8,%9}, {%0,%1,%2,%3};\n"
        : "+f"(d[0]), "+f"(d[1]), "+f"(d[2]), "+f"(d[3])
        : "r"(a[0]), "r"(a[1]), "r"(a[2]), "r"(a[3]), "r"(b[0]), "r"(b[1]));
}

#define AS_STRIDE 20
#define BS_STRIDE 136

template <int KDIM, int MODE, int ASEL>
__global__ void __launch_bounds__(256, 2)
k_mma(const float* __restrict__ Aext, const float* __restrict__ B,
      float* __restrict__ Cext, const float* __restrict__ bias, int M)
{
    const float* A = (ASEL == 0) ? Aext : (ASEL == 1) ? (const float*)g_x1
                                                      : (const float*)g_agg;
    __shared__ unsigned As[128 * AS_STRIDE];
    __shared__ unsigned Bs[16 * BS_STRIDE];

    const int tid = threadIdx.x;
    const int lane = tid & 31;
    const int wid = tid >> 5;
    const int warpM = wid >> 1, warpN = wid & 1;
    const int rowBase = blockIdx.x * 128;

    const int aRow = tid >> 2;
    const int aCol = (tid & 3) * 4;
    const int bRow = tid >> 4;
    const int bCol = (tid & 15) * 4;

    float acc[2][8][4];
    #pragma unroll
    for (int t = 0; t < 2; t++)
        #pragma unroll
        for (int j = 0; j < 8; j++)
            #pragma unroll
            for (int q = 0; q < 4; q++) acc[t][j][q] = 0.f;

    const float4 z4 = make_float4(0.f, 0.f, 0.f, 0.f);
    float4 pa0, pa1, pb0, pb1;

    {   // prefetch k0 = 0
        int r0 = rowBase + aRow;
        pa0 = (r0 < M) ? *(const float4*)&A[(size_t)r0 * KDIM + aCol] : z4;
        int r1 = r0 + 64;
        pa1 = (r1 < M) ? *(const float4*)&A[(size_t)r1 * KDIM + aCol] : z4;
        int j = bRow;
        const float* br = (MODE == 1) ? B + (size_t)(j & 127) * 512 + (size_t)(j >> 7) * 128
                                      : B + (size_t)j * 128;
        pb0 = *(const float4*)&br[bCol];
        pb1 = *(const float4*)&br[bCol + 64];
    }

    for (int k0 = 0; k0 < KDIM; k0 += 16) {
        *(uint4*)&As[aRow * AS_STRIDE + aCol]        = cvt4(pa0);
        *(uint4*)&As[(aRow + 64) * AS_STRIDE + aCol] = cvt4(pa1);
        *(uint4*)&Bs[bRow * BS_STRIDE + bCol]        = cvt4(pb0);
        *(uint4*)&Bs[bRow * BS_STRIDE + bCol + 64]   = cvt4(pb1);
        __syncthreads();

        if (k0 + 16 < KDIM) {
            int kn = k0 + 16;
            int r0 = rowBase + aRow;
            pa0 = (r0 < M) ? *(const float4*)&A[(size_t)r0 * KDIM + kn + aCol] : z4;
            int r1 = r0 + 64;
            pa1 = (r1 < M) ? *(const float4*)&A[(size_t)r1 * KDIM + kn + aCol] : z4;
            int j = kn + bRow;
            const float* br = (MODE == 1) ? B + (size_t)(j & 127) * 512 + (size_t)(j >> 7) * 128
                                          : B + (size_t)j * 128;
            pb0 = *(const float4*)&br[bCol];
            pb1 = *(const float4*)&br[bCol + 64];
        }

        #pragma unroll
        for (int s = 0; s < 2; s++) {
            const int kc = s * 8;
            unsigned af[2][4];
            const int arow = warpM * 32 + (lane >> 2);
            const int acol = kc + (lane & 3);
            #pragma unroll
            for (int t = 0; t < 2; t++) {
                int r = arow + t * 16;
                af[t][0] = As[r * AS_STRIDE + acol];
                af[t][1] = As[(r + 8) * AS_STRIDE + acol];
                af[t][2] = As[r * AS_STRIDE + acol + 4];
                af[t][3] = As[(r + 8) * AS_STRIDE + acol + 4];
            }
            const int bk = kc + (lane & 3);
            #pragma unroll
            for (int j = 0; j < 8; j++) {
                int bn = warpN * 64 + j * 8 + (lane >> 2);
                unsigned bf[2];
                bf[0] = Bs[bk * BS_STRIDE + bn];
                bf[1] = Bs[(bk + 4) * BS_STRIDE + bn];
                #pragma unroll
                for (int t = 0; t < 2; t++)
                    mma_tf32(acc[t][j], af[t], bf);
            }
        }
        __syncthreads();
    }

    #pragma unroll
    for (int t = 0; t < 2; t++) {
        int r0 = rowBase + warpM * 32 + t * 16 + (lane >> 2);
        int r1 = r0 + 8;
        #pragma unroll
        for (int j = 0; j < 8; j++) {
            int c = warpN * 64 + j * 8 + 2 * (lane & 3);
            if (MODE == 0) {
                *(float2*)&g_h[(size_t)r0 * 128 + c] = make_float2(acc[t][j][0], acc[t][j][1]);
                *(float2*)&g_h[(size_t)r1 * 128 + c] = make_float2(acc[t][j][2], acc[t][j][3]);
            } else {
                if (r0 < M) {
                    float v0 = 0.25f * acc[t][j][0] + bias[c]     + g_x2[(size_t)r0 * 128 + c];
                    float v1 = 0.25f * acc[t][j][1] + bias[c + 1] + g_x2[(size_t)r0 * 128 + c + 1];
                    *(float2*)&Cext[(size_t)r0 * 128 + c] = make_float2(v0, v1);
                }
                if (r1 < M) {
                    float v2 = 0.25f * acc[t][j][2] + bias[c]     + g_x2[(size_t)r1 * 128 + c];
                    float v3 = 0.25f * acc[t][j][3] + bias[c + 1] + g_x2[(size_t)r1 * 128 + c + 1];
                    *(float2*)&Cext[(size_t)r1 * 128 + c] = make_float2(v2, v3);
                }
            }
        }
    }
}

// ---------------- per-node softmax + aggregate (layers 1/2) -----------------
// Epilogue also computes NEXT layer's attention scores from the just-produced
// output row (fp32 exact), into the other score buffer (no race).
// LAYER 1: scores in buf A (off 0), out buf B; wv slot 1.
// LAYER 2: scores in buf B, out buf A; wv slot 2.
template <int LAYER>
__global__ void k_agg(const float* __restrict__ xext,
                      const float* __restrict__ bias, int N)
{
    const float* xin = (LAYER == 1) ? xext : (const float*)g_x1;
    float* xout = (LAYER == 1) ? (float*)g_x1 : (float*)g_x2;
    const int rdOff = (LAYER == 1) ? 0 : NCAP * 4;
    const int wrOff = (LAYER == 1) ? NCAP * 4 : 0;

    int warp = (blockIdx.x * blockDim.x + threadIdx.x) >> 5;
    if (warp >= N) return;
    int lane = threadIdx.x & 31;
    int beg = g_off[warp], end = g_off[warp + 1];
    int deg = end - beg;

    const float* ssR = g_ss + rdOff;
    const float* sdR = g_sd + rdOff;

    float4 sdv = *(const float4*)(sdR + 4 * warp);
    float e0 = -1e30f, e1 = -1e30f, e2 = -1e30f, e3 = -1e30f;
    int sl = 0;
    if (lane < deg) {
        sl = g_csrc[beg + lane];
        float4 sv = *(const float4*)(ssR + 4 * sl);
        e0 = lrelu(sv.x + sdv.x); e1 = lrelu(sv.y + sdv.y);
        e2 = lrelu(sv.z + sdv.z); e3 = lrelu(sv.w + sdv.w);
    }
    float m0 = e0, m1 = e1, m2 = e2, m3 = e3;
    for (int i = beg + 32 + lane; i < end; i += 32) {
        int s = g_csrc[i];
        float4 sv = *(const float4*)(ssR + 4 * s);
        m0 = fmaxf(m0, lrelu(sv.x + sdv.x)); m1 = fmaxf(m1, lrelu(sv.y + sdv.y));
        m2 = fmaxf(m2, lrelu(sv.z + sdv.z)); m3 = fmaxf(m3, lrelu(sv.w + sdv.w));
    }
    #pragma unroll
    for (int o = 16; o > 0; o >>= 1) {
        m0 = fmaxf(m0, __shfl_xor_sync(0xffffffffu, m0, o));
        m1 = fmaxf(m1, __shfl_xor_sync(0xffffffffu, m1, o));
        m2 = fmaxf(m2, __shfl_xor_sync(0xffffffffu, m2, o));
        m3 = fmaxf(m3, __shfl_xor_sync(0xffffffffu, m3, o));
    }

    int hsel = lane >> 3;
    float4 vacc = make_float4(0.f, 0.f, 0.f, 0.f);
    float z0 = 0.f, z1 = 0.f, z2 = 0.f, z3 = 0.f;
    int nf = deg < 32 ? deg : 32;
    for (int i = 0; i < nf; i++) {
        float q0 = __shfl_sync(0xffffffffu, e0, i);
        float q1 = __shfl_sync(0xffffffffu, e1, i);
        float q2 = __shfl_sync(0xffffffffu, e2, i);
        float q3 = __shfl_sync(0xffffffffu, e3, i);
        int s = __shfl_sync(0xffffffffu, sl, i);
        float p0 = __expf(q0 - m0), p1 = __expf(q1 - m1);
        float p2 = __expf(q2 - m2), p3 = __expf(q3 - m3);
        z0 += p0; z1 += p1; z2 += p2; z3 += p3;
        float ph = (hsel == 0) ? p0 : (hsel == 1) ? p1 : (hsel == 2) ? p2 : p3;
        float4 row = *(const float4*)&g_h[(size_t)s * 128 + 4 * lane];
        vacc.x += ph * row.x; vacc.y += ph * row.y;
        vacc.z += ph * row.z; vacc.w += ph * row.w;
    }
    for (int i = beg + 32; i < end; i++) {
        int s = g_csrc[i];
        float4 sv = *(const float4*)(ssR + 4 * s);
        float p0 = __expf(lrelu(sv.x + sdv.x) - m0), p1 = __expf(lrelu(sv.y + sdv.y) - m1);
        float p2 = __expf(lrelu(sv.z + sdv.z) - m2), p3 = __expf(lrelu(sv.w + sdv.w) - m3);
        z0 += p0; z1 += p1; z2 += p2; z3 += p3;
        float ph = (hsel == 0) ? p0 : (hsel == 1) ? p1 : (hsel == 2) ? p2 : p3;
        float4 row = *(const float4*)&g_h[(size_t)s * 128 + 4 * lane];
        vacc.x += ph * row.x; vacc.y += ph * row.y;
        vacc.z += ph * row.z; vacc.w += ph * row.w;
    }

    float zh = (hsel == 0) ? z0 : (hsel == 1) ? z1 : (hsel == 2) ? z2 : z3;
    float inv = 1.f / (zh + 1e-16f);
    int f = 4 * lane;
    float4 bi = *(const float4*)&bias[f];
    float4 xi = *(const float4*)&xin[(size_t)warp * 128 + f];
    float4 v;
    v.x = vacc.x * inv + bi.x + xi.x;  v.x = v.x > 0.f ? v.x : expm1f(v.x);
    v.y = vacc.y * inv + bi.y + xi.y;  v.y = v.y > 0.f ? v.y : expm1f(v.y);
    v.z = vacc.z * inv + bi.z + xi.z;  v.z = v.z > 0.f ? v.z : expm1f(v.z);
    v.w = vacc.w * inv + bi.w + xi.w;  v.w = v.w > 0.f ? v.w : expm1f(v.w);
    *(float4*)&xout[(size_t)warp * 128 + f] = v;

    // ---- fused next-layer scores (fp32 exact, write other buffer) ----
    {
        const float* wvs = g_wvs + LAYER * 512;   // slot 1 (layer2) or 2 (layer3)
        const float* wvd = g_wvd + LAYER * 512;
        float xv4[4] = {v.x, v.y, v.z, v.w};
        float ps[4] = {0.f, 0.f, 0.f, 0.f}, pd[4] = {0.f, 0.f, 0.f, 0.f};
        #pragma unroll
        for (int q = 0; q < 4; q++) {
            int k = f + q;
            float4 vs = *(const float4*)&wvs[k * 4];
            float4 vd = *(const float4*)&wvd[k * 4];
            ps[0] += xv4[q] * vs.x; ps[1] += xv4[q] * vs.y;
            ps[2] += xv4[q] * vs.z; ps[3] += xv4[q] * vs.w;
            pd[0] += xv4[q] * vd.x; pd[1] += xv4[q] * vd.y;
            pd[2] += xv4[q] * vd.z; pd[3] += xv4[q] * vd.w;
        }
        #pragma unroll
        for (int o = 16; o > 0; o >>= 1)
            #pragma unroll
            for (int hh = 0; hh < 4; hh++) {
                ps[hh] += __shfl_xor_sync(0xffffffffu, ps[hh], o);
                pd[hh] += __shfl_xor_sync(0xffffffffu, pd[hh], o);
            }
        if (lane == 0) {
            *(float4*)&g_ss[wrOff + warp * 4] = make_float4(ps[0], ps[1], ps[2], ps[3]);
            *(float4*)&g_sd[wrOff + warp * 4] = make_float4(pd[0], pd[1], pd[2], pd[3]);
        }
    }
}

// ---------------- layer-3 aggregate: agg[n,h*128+k] = sum_e alpha_h x2[src,k]
// Scores in buffer A (written by k_agg<2>).
__global__ void k_agg3(int N)
{
    int warp = (blockIdx.x * blockDim.x + threadIdx.x) >> 5;
    if (warp >= N) return;
    int lane = threadIdx.x & 31;
    int beg = g_off[warp], end = g_off[warp + 1];
    int deg = end - beg;

    float4 sdv = *(const float4*)(g_sd + 4 * warp);
    float e0 = -1e30f, e1 = -1e30f, e2 = -1e30f, e3 = -1e30f;
    int sl = 0;
    if (lane < deg) {
        sl = g_csrc[beg + lane];
        float4 sv = *(const float4*)(g_ss + 4 * sl);
        e0 = lrelu(sv.x + sdv.x); e1 = lrelu(sv.y + sdv.y);
        e2 = lrelu(sv.z + sdv.z); e3 = lrelu(sv.w + sdv.w);
    }
    float m0 = e0, m1 = e1, m2 = e2, m3 = e3;
    for (int i = beg + 32 + lane; i < end; i += 32) {
        int s = g_csrc[i];
        float4 sv = *(const float4*)(g_ss + 4 * s);
        m0 = fmaxf(m0, lrelu(sv.x + sdv.x)); m1 = fmaxf(m1, lrelu(sv.y + sdv.y));
        m2 = fmaxf(m2, lrelu(sv.z + sdv.z)); m3 = fmaxf(m3, lrelu(sv.w + sdv.w));
    }
    #pragma unroll
    for (int o = 16; o > 0; o >>= 1) {
        m0 = fmaxf(m0, __shfl_xor_sync(0xffffffffu, m0, o));
        m1 = fmaxf(m1, __shfl_xor_sync(0xffffffffu, m1, o));
        m2 = fmaxf(m2, __shfl_xor_sync(0xffffffffu, m2, o));
        m3 = fmaxf(m3, __shfl_xor_sync(0xffffffffu, m3, o));
    }

    float4 va0 = make_float4(0,0,0,0), va1 = va0, va2 = va0, va3 = va0;
    float z0 = 0.f, z1 = 0.f, z2 = 0.f, z3 = 0.f;
    int nf = deg < 32 ? deg : 32;
    for (int i = 0; i < nf; i++) {
        float q0 = __shfl_sync(0xffffffffu, e0, i);
        float q1 = __shfl_sync(0xffffffffu, e1, i);
        float q2 = __shfl_sync(0xffffffffu, e2, i);
        float q3 = __shfl_sync(0xffffffffu, e3, i);
        int s = __shfl_sync(0xffffffffu, sl, i);
        float p0 = __expf(q0 - m0), p1 = __expf(q1 - m1);
        float p2 = __expf(q2 - m2), p3 = __expf(q3 - m3);
        z0 += p0; z1 += p1; z2 += p2; z3 += p3;
        float4 row = *(const float4*)&g_x2[(size_t)s * 128 + 4 * lane];
        va0.x += p0*row.x; va0.y += p0*row.y; va0.z += p0*row.z; va0.w += p0*row.w;
        va1.x += p1*row.x; va1.y += p1*row.y; va1.z += p1*row.z; va1.w += p1*row.w;
        va2.x += p2*row.x; va2.y += p2*row.y; va2.z += p2*row.z; va2.w += p2*row.w;
        va3.x += p3*row.x; va3.y += p3*row.y; va3.z += p3*row.z; va3.w += p3*row.w;
    }
    for (int i = beg + 32; i < end; i++) {
        int s = g_csrc[i];
        float4 sv = *(const float4*)(g_ss + 4 * s);
        float p0 = __expf(lrelu(sv.x + sdv.x) - m0), p1 = __expf(lrelu(sv.y + sdv.y) - m1);
        float p2 = __expf(lrelu(sv.z + sdv.z) - m2), p3 = __expf(lrelu(sv.w + sdv.w) - m3);
        z0 += p0; z1 += p1; z2 += p2; z3 += p3;
        float4 row = *(const float4*)&g_x2[(size_t)s * 128 + 4 * lane];
        va0.x += p0*row.x; va0.y += p0*row.y; va0.z += p0*row.z; va0.w += p0*row.w;
        va1.x += p1*row.x; va1.y += p1*row.y; va1.z += p1*row.z; va1.w += p1*row.w;
        va2.x += p2*row.x; va2.y += p2*row.y; va2.z += p2*row.z; va2.w += p2*row.w;
        va3.x += p3*row.x; va3.y += p3*row.y; va3.z += p3*row.z; va3.w += p3*row.w;
    }

    float i0 = 1.f/(z0+1e-16f), i1 = 1.f/(z1+1e-16f), i2 = 1.f/(z2+1e-16f), i3 = 1.f/(z3+1e-16f);
    size_t base = (size_t)warp * 512 + 4 * lane;
    *(float4*)&g_agg[base]       = make_float4(va0.x*i0, va0.y*i0, va0.z*i0, va0.w*i0);
    *(float4*)&g_agg[base + 128] = make_float4(va1.x*i1, va1.y*i1, va1.z*i1, va1.w*i1);
    *(float4*)&g_agg[base + 256] = make_float4(va2.x*i2, va2.y*i2, va2.z*i2, va2.w*i2);
    *(float4*)&g_agg[base + 384] = make_float4(va3.x*i3, va3.y*i3, va3.z*i3, va3.w*i3);
}

// ---------------- host entry ----------------
extern "C" void kernel_launch(void* const* d_in, const int* in_sizes, int n_in,
                              void* d_out, int out_size)
{
    const float* x   = (const float*)d_in[0];
    const void*  ei  = d_in[1];
    const float* W1  = (const float*)d_in[2];
    const float* as1 = (const float*)d_in[3];
    const float* ad1 = (const float*)d_in[4];
    const float* b1  = (const float*)d_in[5];
    const float* W2  = (const float*)d_in[6];
    const float* as2 = (const float*)d_in[7];
    const float* ad2 = (const float*)d_in[8];
    const float* b2  = (const float*)d_in[9];
    const float* W3  = (const float*)d_in[10];
    const float* as3 = (const float*)d_in[11];
    const float* ad3 = (const float*)d_in[12];
    const float* b3  = (const float*)d_in[13];

    int N = in_sizes[0] / 128;
    int E = in_sizes[1] / 2;

    int nb = (N + 1023) / 1024;
    int nsamp = (2 * E < 8192) ? 2 * E : 8192;

    // edge dtype detect + CSR build + score-vector precompute
    k_detect<<<1, 512>>>((const int*)ei, nsamp);
    k_init_cnt<<<nb, 1024>>>(N);
    k_hist<<<(E + 255) / 256, 256>>>(ei, E, N);
    k_wvec<0><<<4, 256>>>(W1, as1, ad1);
    k_wvec<1><<<4, 256>>>(W2, as2, ad2);
    k_wvec<2><<<4, 256>>>(W3, as3, ad3);
    k_scan1<<<nb, 1024>>>(N);
    k_scan2<<<1, 1024>>>(nb);
    k_scan3<<<nb, 1024>>>(N);
    k_scatter<<<(E + N + 255) / 256, 256>>>(ei, E, N);

    int gemmBlocks = (N + 127) / 128;
    int aggBlocks  = (N + 7) / 8;   // 8 warps (nodes) per 256-thread block

    // layer 1: exact fp32 scores from x (buf A); tf32 GEMM; agg -> x1 + L2 scores (buf B)
    k_scores1<<<aggBlocks, 256>>>(x, N);
    k_mma<128, 0, 0><<<gemmBlocks, 256>>>(x, W1, nullptr, nullptr, N);
    k_agg<1><<<aggBlocks, 256>>>(x, b1, N);

    // layer 2: agg -> x2 + L3 scores (buf A)
    k_mma<128, 0, 1><<<gemmBlocks, 256>>>(nullptr, W2, nullptr, nullptr, N);
    k_agg<2><<<aggBlocks, 256>>>(nullptr, b2, N);

    // layer 3 (never materializes h3 = [N,4,128])
    k_agg3<<<aggBlocks, 256>>>(N);
    k_mma<512, 1, 2><<<gemmBlocks, 256>>>(nullptr, W3, (float*)d_out, b3, N);
}

// round 17
// speedup vs baseline: 1.5449x; 1.0383x over previous
#include <cuda_runtime.h>
#include <math.h>

// Problem caps (N=100000, E=800000 per setup_inputs; small safety margin)
#define NCAP 100352
#define ECAP 802816
#define ETCAP (ECAP + NCAP)

// R17 = resubmission of R13..R16 (repeated broker/container infra failures;
// kernel never executed). Hypothesis: lane-owned exp + z warp-reduction in
// the aggregation kernels.

// ---------------- device scratch (static, no allocation) ----------------
__device__ float g_h  [(size_t)NCAP * 128];   // per-layer transformed features
__device__ float g_x1 [(size_t)NCAP * 128];   // layer-1 output
__device__ float g_x2 [(size_t)NCAP * 128];   // layer-2 output
__device__ float g_agg[(size_t)NCAP * 512];   // layer-3 weighted x2 aggregate
__device__ float g_ss [2 * NCAP * 4];         // s_src, double-buffered (A=0, B=1)
__device__ float g_sd [2 * NCAP * 4];         // s_dst, double-buffered
__device__ int   g_cnt [NCAP];
__device__ int   g_scan[NCAP];
__device__ int   g_bsum[1024];
__device__ int   g_off [NCAP + 1];
__device__ int   g_cur [NCAP];
__device__ int   g_csrc[ETCAP];
__device__ float g_wvs[3 * 512];              // per-layer W@a_src  [128,4]
__device__ float g_wvd[3 * 512];              // per-layer W@a_dst  [128,4]
__device__ int   g_i64;                       // 1 if edge_index is int64, 0 if int32

__device__ __forceinline__ float lrelu(float e) { return e > 0.f ? e : 0.2f * e; }

__device__ __forceinline__ int edge_at(const void* ei, int idx) {
    if (g_i64) return (int)((const long long*)ei)[idx];
    return ((const int*)ei)[idx];
}

// ---------------- init counts + edge dtype detection (merged) ----------------
__global__ void k_init(const int* __restrict__ ei32, int nsamp, int N) {
    int i = blockIdx.x * blockDim.x + threadIdx.x;
    if (i < N) g_cnt[i] = 1;   // self loop
    if (blockIdx.x == 0) {
        __shared__ int any;
        if (threadIdx.x == 0) any = 0;
        __syncthreads();
        for (int j = threadIdx.x * 2 + 1; j < nsamp; j += 2048)
            if (ei32[j] != 0) { any = 1; break; }
        __syncthreads();
        if (threadIdx.x == 0) g_i64 = any ? 0 : 1;
    }
}

__global__ void k_hist(const void* __restrict__ ei, int E, int N) {
    int e = blockIdx.x * blockDim.x + threadIdx.x;
    if (e >= E) return;
    int dst = edge_at(ei, E + e);
    if ((unsigned)dst < (unsigned)N) atomicAdd(&g_cnt[dst], 1);
}

__global__ void k_scan1(int N) {
    __shared__ int sm[1024];
    int tid = threadIdx.x;
    int i = blockIdx.x * 1024 + tid;
    sm[tid] = (i < N) ? g_cnt[i] : 0;
    __syncthreads();
    for (int off = 1; off < 1024; off <<= 1) {
        int t = (tid >= off) ? sm[tid - off] : 0;
        __syncthreads();
        sm[tid] += t;
        __syncthreads();
    }
    if (i < N) g_scan[i] = sm[tid];
    if (tid == 1023) g_bsum[blockIdx.x] = sm[1023];
}

__global__ void k_scan2(int nb) {
    __shared__ int sm[1024];
    int tid = threadIdx.x;
    sm[tid] = (tid < nb) ? g_bsum[tid] : 0;
    __syncthreads();
    for (int off = 1; off < 1024; off <<= 1) {
        int t = (tid >= off) ? sm[tid - off] : 0;
        __syncthreads();
        sm[tid] += t;
        __syncthreads();
    }
    if (tid < nb) g_bsum[tid] = sm[tid];
}

__global__ void k_scan3(int N) {
    int i = blockIdx.x * 1024 + threadIdx.x;
    if (i >= N) return;
    int pre = (blockIdx.x > 0) ? g_bsum[blockIdx.x - 1] : 0;
    int inc = g_scan[i] + pre;
    g_off[i + 1] = inc;
    g_cur[i] = inc - g_cnt[i];
    if (i == 0) g_off[0] = 0;
}

__global__ void k_scatter(const void* __restrict__ ei, int E, int N) {
    int t = blockIdx.x * blockDim.x + threadIdx.x;
    int src, dst;
    if (t < E) {
        src = edge_at(ei, t);
        dst = edge_at(ei, E + t);
        if ((unsigned)src >= (unsigned)N || (unsigned)dst >= (unsigned)N) return;
    }
    else if (t < E + N) { src = dst = t - E; }
    else return;
    int pos = atomicAdd(&g_cur[dst], 1);
    g_csrc[pos] = src;
}

// ---------------- pre-contracted score vectors (all 3 layers, one launch) ----
// Layers 1/2 (C=32): wv[k][h] = sum_{c<32}  W[k,h*32+c]  * a[h,c]
// Layer  3  (C=128): wv[k][h] = sum_{f<128} W3[k,h*128+f]* a[h,f]
__global__ void k_wvec_all(const float* __restrict__ W1, const float* __restrict__ as1,
                           const float* __restrict__ ad1,
                           const float* __restrict__ W2, const float* __restrict__ as2,
                           const float* __restrict__ ad2,
                           const float* __restrict__ W3, const float* __restrict__ as3,
                           const float* __restrict__ ad3)
{
    int L = blockIdx.y;
    const float* W  = (L == 0) ? W1  : (L == 1) ? W2  : W3;
    const float* as = (L == 0) ? as1 : (L == 1) ? as2 : as3;
    const float* ad = (L == 0) ? ad1 : (L == 1) ? ad2 : ad3;
    int t = blockIdx.x * blockDim.x + threadIdx.x;
    if (t >= 1024) return;
    int which = t >> 9;
    int idx = t & 511;
    int k = idx >> 2, hh = idx & 3;
    const float* a = which ? ad : as;
    float s = 0.f;
    if (L < 2) {
        const float* wr = W + (size_t)k * 128 + hh * 32;
        const float* ar = a + hh * 32;
        for (int c = 0; c < 32; c++) s += wr[c] * ar[c];
    } else {
        const float* wr = W + (size_t)k * 512 + hh * 128;
        const float* ar = a + hh * 128;
        for (int f = 0; f < 128; f++) s += wr[f] * ar[f];
    }
    (which ? g_wvd : g_wvs)[L * 512 + k * 4 + hh] = s;
}

// ---------------- layer-1 scores from x (exact fp32) -> buffer A ----------
__global__ void k_scores1(const float* __restrict__ X, int N)
{
    int warp = (blockIdx.x * blockDim.x + threadIdx.x) >> 5;
    if (warp >= N) return;
    int lane = threadIdx.x & 31;
    const float* xr = X + (size_t)warp * 128;
    float ps[4] = {0.f, 0.f, 0.f, 0.f}, pd[4] = {0.f, 0.f, 0.f, 0.f};
    #pragma unroll
    for (int kk = 0; kk < 4; kk++) {
        int k = kk * 32 + lane;
        float xv = xr[k];
        float4 vs = *(const float4*)&g_wvs[k * 4];
        float4 vd = *(const float4*)&g_wvd[k * 4];
        ps[0] += xv * vs.x; ps[1] += xv * vs.y; ps[2] += xv * vs.z; ps[3] += xv * vs.w;
        pd[0] += xv * vd.x; pd[1] += xv * vd.y; pd[2] += xv * vd.z; pd[3] += xv * vd.w;
    }
    #pragma unroll
    for (int o = 16; o > 0; o >>= 1)
        #pragma unroll
        for (int hh = 0; hh < 4; hh++) {
            ps[hh] += __shfl_xor_sync(0xffffffffu, ps[hh], o);
            pd[hh] += __shfl_xor_sync(0xffffffffu, pd[hh], o);
        }
    if (lane == 0) {
        *(float4*)&g_ss[warp * 4] = make_float4(ps[0], ps[1], ps[2], ps[3]);
        *(float4*)&g_sd[warp * 4] = make_float4(pd[0], pd[1], pd[2], pd[3]);
    }
}

// ---------------- TF32 tensor-core GEMM (single-pass) ----------------
__device__ __forceinline__ unsigned f2tf(float f) {
    unsigned u;
    asm("cvt.rna.tf32.f32 %0, %1;" : "=r"(u) : "f"(f));
    return u;
}
__device__ __forceinline__ uint4 cvt4(float4 v) {
    uint4 u;
    u.x = f2tf(v.x); u.y = f2tf(v.y); u.z = f2tf(v.z); u.w = f2tf(v.w);
    return u;
}
__device__ __forceinline__ void mma_tf32(float* d, const unsigned* a, const unsigned* b) {
    asm volatile(
        "mma.sync.aligned.m16n8k8.row.col.f32.tf32.tf32.f32 "
        "{%0,%1,%2,%3}, {%4,%5,%6,%7}, {%8,%9}, {%0,%1,%2,%3};\n"
        : "+f"(d[0]), "+f"(d[1]), "+f"(d[2]), "+f"(d[3])
        : "r"(a[0]), "r"(a[1]), "r"(a[2]), "r"(a[3]), "r"(b[0]), "r"(b[1]));
}

#define AS_STRIDE 20
#define BS_STRIDE 136

template <int KDIM, int MODE, int ASEL>
__global__ void __launch_bounds__(256, 2)
k_mma(const float* __restrict__ Aext, const float* __restrict__ B,
      float* __restrict__ Cext, const float* __restrict__ bias, int M)
{
    const float* A = (ASEL == 0) ? Aext : (ASEL == 1) ? (const float*)g_x1
                                                      : (const float*)g_agg;
    __shared__ unsigned As[128 * AS_STRIDE];
    __shared__ unsigned Bs[16 * BS_STRIDE];

    const int tid = threadIdx.x;
    const int lane = tid & 31;
    const int wid = tid >> 5;
    const int warpM = wid >> 1, warpN = wid & 1;
    const int rowBase = blockIdx.x * 128;

    const int aRow = tid >> 2;
    const int aCol = (tid & 3) * 4;
    const int bRow = tid >> 4;
    const int bCol = (tid & 15) * 4;

    float acc[2][8][4];
    #pragma unroll
    for (int t = 0; t < 2; t++)
        #pragma unroll
        for (int j = 0; j < 8; j++)
            #pragma unroll
            for (int q = 0; q < 4; q++) acc[t][j][q] = 0.f;

    const float4 z4 = make_float4(0.f, 0.f, 0.f, 0.f);
    float4 pa0, pa1, pb0, pb1;

    {   // prefetch k0 = 0
        int r0 = rowBase + aRow;
        pa0 = (r0 < M) ? *(const float4*)&A[(size_t)r0 * KDIM + aCol] : z4;
        int r1 = r0 + 64;
        pa1 = (r1 < M) ? *(const float4*)&A[(size_t)r1 * KDIM + aCol] : z4;
        int j = bRow;
        const float* br = (MODE == 1) ? B + (size_t)(j & 127) * 512 + (size_t)(j >> 7) * 128
                                      : B + (size_t)j * 128;
        pb0 = *(const float4*)&br[bCol];
        pb1 = *(const float4*)&br[bCol + 64];
    }

    for (int k0 = 0; k0 < KDIM; k0 += 16) {
        *(uint4*)&As[aRow * AS_STRIDE + aCol]        = cvt4(pa0);
        *(uint4*)&As[(aRow + 64) * AS_STRIDE + aCol] = cvt4(pa1);
        *(uint4*)&Bs[bRow * BS_STRIDE + bCol]        = cvt4(pb0);
        *(uint4*)&Bs[bRow * BS_STRIDE + bCol + 64]   = cvt4(pb1);
        __syncthreads();

        if (k0 + 16 < KDIM) {
            int kn = k0 + 16;
            int r0 = rowBase + aRow;
            pa0 = (r0 < M) ? *(const float4*)&A[(size_t)r0 * KDIM + kn + aCol] : z4;
            int r1 = r0 + 64;
            pa1 = (r1 < M) ? *(const float4*)&A[(size_t)r1 * KDIM + kn + aCol] : z4;
            int j = kn + bRow;
            const float* br = (MODE == 1) ? B + (size_t)(j & 127) * 512 + (size_t)(j >> 7) * 128
                                          : B + (size_t)j * 128;
            pb0 = *(const float4*)&br[bCol];
            pb1 = *(const float4*)&br[bCol + 64];
        }

        #pragma unroll
        for (int s = 0; s < 2; s++) {
            const int kc = s * 8;
            unsigned af[2][4];
            const int arow = warpM * 32 + (lane >> 2);
            const int acol = kc + (lane & 3);
            #pragma unroll
            for (int t = 0; t < 2; t++) {
                int r = arow + t * 16;
                af[t][0] = As[r * AS_STRIDE + acol];
                af[t][1] = As[(r + 8) * AS_STRIDE + acol];
                af[t][2] = As[r * AS_STRIDE + acol + 4];
                af[t][3] = As[(r + 8) * AS_STRIDE + acol + 4];
            }
            const int bk = kc + (lane & 3);
            #pragma unroll
            for (int j = 0; j < 8; j++) {
                int bn = warpN * 64 + j * 8 + (lane >> 2);
                unsigned bf[2];
                bf[0] = Bs[bk * BS_STRIDE + bn];
                bf[1] = Bs[(bk + 4) * BS_STRIDE + bn];
                #pragma unroll
                for (int t = 0; t < 2; t++)
                    mma_tf32(acc[t][j], af[t], bf);
            }
        }
        __syncthreads();
    }

    #pragma unroll
    for (int t = 0; t < 2; t++) {
        int r0 = rowBase + warpM * 32 + t * 16 + (lane >> 2);
        int r1 = r0 + 8;
        #pragma unroll
        for (int j = 0; j < 8; j++) {
            int c = warpN * 64 + j * 8 + 2 * (lane & 3);
            if (MODE == 0) {
                *(float2*)&g_h[(size_t)r0 * 128 + c] = make_float2(acc[t][j][0], acc[t][j][1]);
                *(float2*)&g_h[(size_t)r1 * 128 + c] = make_float2(acc[t][j][2], acc[t][j][3]);
            } else {
                if (r0 < M) {
                    float v0 = 0.25f * acc[t][j][0] + bias[c]     + g_x2[(size_t)r0 * 128 + c];
                    float v1 = 0.25f * acc[t][j][1] + bias[c + 1] + g_x2[(size_t)r0 * 128 + c + 1];
                    *(float2*)&Cext[(size_t)r0 * 128 + c] = make_float2(v0, v1);
                }
                if (r1 < M) {
                    float v2 = 0.25f * acc[t][j][2] + bias[c]     + g_x2[(size_t)r1 * 128 + c];
                    float v3 = 0.25f * acc[t][j][3] + bias[c + 1] + g_x2[(size_t)r1 * 128 + c + 1];
                    *(float2*)&Cext[(size_t)r1 * 128 + c] = make_float2(v2, v3);
                }
            }
        }
    }
}

// ---------------- per-node softmax + aggregate (layers 1/2) -----------------
// Lane-owned edge scores; exp computed ONCE per edge in the owning lane
// (parallel across edges), p broadcast via shfl; z by warp reduction.
// Epilogue computes NEXT layer's scores into the other buffer.
template <int LAYER>
__global__ void k_agg(const float* __restrict__ xext,
                      const float* __restrict__ bias, int N)
{
    const float* xin = (LAYER == 1) ? xext : (const float*)g_x1;
    float* xout = (LAYER == 1) ? (float*)g_x1 : (float*)g_x2;
    const int rdOff = (LAYER == 1) ? 0 : NCAP * 4;
    const int wrOff = (LAYER == 1) ? NCAP * 4 : 0;

    int warp = (blockIdx.x * blockDim.x + threadIdx.x) >> 5;
    if (warp >= N) return;
    int lane = threadIdx.x & 31;
    int beg = g_off[warp], end = g_off[warp + 1];
    int deg = end - beg;

    const float* ssR = g_ss + rdOff;
    const float* sdR = g_sd + rdOff;

    float4 sdv = *(const float4*)(sdR + 4 * warp);
    float e0 = -1e30f, e1 = -1e30f, e2 = -1e30f, e3 = -1e30f;
    int sl = 0;
    if (lane < deg) {
        sl = g_csrc[beg + lane];
        float4 sv = *(const float4*)(ssR + 4 * sl);
        e0 = lrelu(sv.x + sdv.x); e1 = lrelu(sv.y + sdv.y);
        e2 = lrelu(sv.z + sdv.z); e3 = lrelu(sv.w + sdv.w);
    }
    float m0 = e0, m1 = e1, m2 = e2, m3 = e3;
    for (int i = beg + 32 + lane; i < end; i += 32) {   // rare: deg > 32
        int s = g_csrc[i];
        float4 sv = *(const float4*)(ssR + 4 * s);
        m0 = fmaxf(m0, lrelu(sv.x + sdv.x)); m1 = fmaxf(m1, lrelu(sv.y + sdv.y));
        m2 = fmaxf(m2, lrelu(sv.z + sdv.z)); m3 = fmaxf(m3, lrelu(sv.w + sdv.w));
    }
    #pragma unroll
    for (int o = 16; o > 0; o >>= 1) {
        m0 = fmaxf(m0, __shfl_xor_sync(0xffffffffu, m0, o));
        m1 = fmaxf(m1, __shfl_xor_sync(0xffffffffu, m1, o));
        m2 = fmaxf(m2, __shfl_xor_sync(0xffffffffu, m2, o));
        m3 = fmaxf(m3, __shfl_xor_sync(0xffffffffu, m3, o));
    }

    // owning lane computes p once (lanes >= deg give exp(-inf)=0)
    float p0 = __expf(e0 - m0), p1 = __expf(e1 - m1);
    float p2 = __expf(e2 - m2), p3 = __expf(e3 - m3);

    // z by warp reduction
    float z0 = p0, z1 = p1, z2 = p2, z3 = p3;
    #pragma unroll
    for (int o = 16; o > 0; o >>= 1) {
        z0 += __shfl_xor_sync(0xffffffffu, z0, o);
        z1 += __shfl_xor_sync(0xffffffffu, z1, o);
        z2 += __shfl_xor_sync(0xffffffffu, z2, o);
        z3 += __shfl_xor_sync(0xffffffffu, z3, o);
    }

    int hsel = lane >> 3;
    float4 vacc = make_float4(0.f, 0.f, 0.f, 0.f);
    int nf = deg < 32 ? deg : 32;
    for (int i = 0; i < nf; i++) {
        float q0 = __shfl_sync(0xffffffffu, p0, i);
        float q1 = __shfl_sync(0xffffffffu, p1, i);
        float q2 = __shfl_sync(0xffffffffu, p2, i);
        float q3 = __shfl_sync(0xffffffffu, p3, i);
        int s = __shfl_sync(0xffffffffu, sl, i);
        float ph = (hsel == 0) ? q0 : (hsel == 1) ? q1 : (hsel == 2) ? q2 : q3;
        float4 row = *(const float4*)&g_h[(size_t)s * 128 + 4 * lane];
        vacc.x += ph * row.x; vacc.y += ph * row.y;
        vacc.z += ph * row.z; vacc.w += ph * row.w;
    }
    for (int i = beg + 32; i < end; i++) {              // rare tail
        int s = g_csrc[i];
        float4 sv = *(const float4*)(ssR + 4 * s);
        float t0 = __expf(lrelu(sv.x + sdv.x) - m0), t1 = __expf(lrelu(sv.y + sdv.y) - m1);
        float t2 = __expf(lrelu(sv.z + sdv.z) - m2), t3 = __expf(lrelu(sv.w + sdv.w) - m3);
        z0 += t0; z1 += t1; z2 += t2; z3 += t3;   // uniform across lanes
        float ph = (hsel == 0) ? t0 : (hsel == 1) ? t1 : (hsel == 2) ? t2 : t3;
        float4 row = *(const float4*)&g_h[(size_t)s * 128 + 4 * lane];
        vacc.x += ph * row.x; vacc.y += ph * row.y;
        vacc.z += ph * row.z; vacc.w += ph * row.w;
    }

    float zh = (hsel == 0) ? z0 : (hsel == 1) ? z1 : (hsel == 2) ? z2 : z3;
    float inv = 1.f / (zh + 1e-16f);
    int f = 4 * lane;
    float4 bi = *(const float4*)&bias[f];
    float4 xi = *(const float4*)&xin[(size_t)warp * 128 + f];
    float4 v;
    v.x = vacc.x * inv + bi.x + xi.x;  v.x = v.x > 0.f ? v.x : expm1f(v.x);
    v.y = vacc.y * inv + bi.y + xi.y;  v.y = v.y > 0.f ? v.y : expm1f(v.y);
    v.z = vacc.z * inv + bi.z + xi.z;  v.z = v.z > 0.f ? v.z : expm1f(v.z);
    v.w = vacc.w * inv + bi.w + xi.w;  v.w = v.w > 0.f ? v.w : expm1f(v.w);
    *(float4*)&xout[(size_t)warp * 128 + f] = v;

    // ---- fused next-layer scores (fp32 exact, write other buffer) ----
    {
        const float* wvs = g_wvs + LAYER * 512;
        const float* wvd = g_wvd + LAYER * 512;
        float xv4[4] = {v.x, v.y, v.z, v.w};
        float ps[4] = {0.f, 0.f, 0.f, 0.f}, pd[4] = {0.f, 0.f, 0.f, 0.f};
        #pragma unroll
        for (int q = 0; q < 4; q++) {
            int k = f + q;
            float4 vs = *(const float4*)&wvs[k * 4];
            float4 vd = *(const float4*)&wvd[k * 4];
            ps[0] += xv4[q] * vs.x; ps[1] += xv4[q] * vs.y;
            ps[2] += xv4[q] * vs.z; ps[3] += xv4[q] * vs.w;
            pd[0] += xv4[q] * vd.x; pd[1] += xv4[q] * vd.y;
            pd[2] += xv4[q] * vd.z; pd[3] += xv4[q] * vd.w;
        }
        #pragma unroll
        for (int o = 16; o > 0; o >>= 1)
            #pragma unroll
            for (int hh = 0; hh < 4; hh++) {
                ps[hh] += __shfl_xor_sync(0xffffffffu, ps[hh], o);
                pd[hh] += __shfl_xor_sync(0xffffffffu, pd[hh], o);
            }
        if (lane == 0) {
            *(float4*)&g_ss[wrOff + warp * 4] = make_float4(ps[0], ps[1], ps[2], ps[3]);
            *(float4*)&g_sd[wrOff + warp * 4] = make_float4(pd[0], pd[1], pd[2], pd[3]);
        }
    }
}

// ---------------- layer-3 aggregate: agg[n,h*128+k] = sum_e alpha_h x2[src,k]
// Scores in buffer A (written by k_agg<2>). Same lane-owned-p restructure.
__global__ void k_agg3(int N)
{
    int warp = (blockIdx.x * blockDim.x + threadIdx.x) >> 5;
    if (warp >= N) return;
    int lane = threadIdx.x & 31;
    int beg = g_off[warp], end = g_off[warp + 1];
    int deg = end - beg;

    float4 sdv = *(const float4*)(g_sd + 4 * warp);
    float e0 = -1e30f, e1 = -1e30f, e2 = -1e30f, e3 = -1e30f;
    int sl = 0;
    if (lane < deg) {
        sl = g_csrc[beg + lane];
        float4 sv = *(const float4*)(g_ss + 4 * sl);
        e0 = lrelu(sv.x + sdv.x); e1 = lrelu(sv.y + sdv.y);
        e2 = lrelu(sv.z + sdv.z); e3 = lrelu(sv.w + sdv.w);
    }
    float m0 = e0, m1 = e1, m2 = e2, m3 = e3;
    for (int i = beg + 32 + lane; i < end; i += 32) {
        int s = g_csrc[i];
        float4 sv = *(const float4*)(g_ss + 4 * s);
        m0 = fmaxf(m0, lrelu(sv.x + sdv.x)); m1 = fmaxf(m1, lrelu(sv.y + sdv.y));
        m2 = fmaxf(m2, lrelu(sv.z + sdv.z)); m3 = fmaxf(m3, lrelu(sv.w + sdv.w));
    }
    #pragma unroll
    for (int o = 16; o > 0; o >>= 1) {
        m0 = fmaxf(m0, __shfl_xor_sync(0xffffffffu, m0, o));
        m1 = fmaxf(m1, __shfl_xor_sync(0xffffffffu, m1, o));
        m2 = fmaxf(m2, __shfl_xor_sync(0xffffffffu, m2, o));
        m3 = fmaxf(m3, __shfl_xor_sync(0xffffffffu, m3, o));
    }

    float p0 = __expf(e0 - m0), p1 = __expf(e1 - m1);
    float p2 = __expf(e2 - m2), p3 = __expf(e3 - m3);

    float z0 = p0, z1 = p1, z2 = p2, z3 = p3;
    #pragma unroll
    for (int o = 16; o > 0; o >>= 1) {
        z0 += __shfl_xor_sync(0xffffffffu, z0, o);
        z1 += __shfl_xor_sync(0xffffffffu, z1, o);
        z2 += __shfl_xor_sync(0xffffffffu, z2, o);
        z3 += __shfl_xor_sync(0xffffffffu, z3, o);
    }

    float4 va0 = make_float4(0,0,0,0), va1 = va0, va2 = va0, va3 = va0;
    int nf = deg < 32 ? deg : 32;
    for (int i = 0; i < nf; i++) {
        float q0 = __shfl_sync(0xffffffffu, p0, i);
        float q1 = __shfl_sync(0xffffffffu, p1, i);
        float q2 = __shfl_sync(0xffffffffu, p2, i);
        float q3 = __shfl_sync(0xffffffffu, p3, i);
        int s = __shfl_sync(0xffffffffu, sl, i);
        float4 row = *(const float4*)&g_x2[(size_t)s * 128 + 4 * lane];
        va0.x += q0*row.x; va0.y += q0*row.y; va0.z += q0*row.z; va0.w += q0*row.w;
        va1.x += q1*row.x; va1.y += q1*row.y; va1.z += q1*row.z; va1.w += q1*row.w;
        va2.x += q2*row.x; va2.y += q2*row.y; va2.z += q2*row.z; va2.w += q2*row.w;
        va3.x += q3*row.x; va3.y += q3*row.y; va3.z += q3*row.z; va3.w += q3*row.w;
    }
    for (int i = beg + 32; i < end; i++) {
        int s = g_csrc[i];
        float4 sv = *(const float4*)(g_ss + 4 * s);
        float t0 = __expf(lrelu(sv.x + sdv.x) - m0), t1 = __expf(lrelu(sv.y + sdv.y) - m1);
        float t2 = __expf(lrelu(sv.z + sdv.z) - m2), t3 = __expf(lrelu(sv.w + sdv.w) - m3);
        z0 += t0; z1 += t1; z2 += t2; z3 += t3;
        float4 row = *(const float4*)&g_x2[(size_t)s * 128 + 4 * lane];
        va0.x += t0*row.x; va0.y += t0*row.y; va0.z += t0*row.z; va0.w += t0*row.w;
        va1.x += t1*row.x; va1.y += t1*row.y; va1.z += t1*row.z; va1.w += t1*row.w;
        va2.x += t2*row.x; va2.y += t2*row.y; va2.z += t2*row.z; va2.w += t2*row.w;
        va3.x += t3*row.x; va3.y += t3*row.y; va3.z += t3*row.z; va3.w += t3*row.w;
    }

    float i0 = 1.f/(z0+1e-16f), i1 = 1.f/(z1+1e-16f), i2 = 1.f/(z2+1e-16f), i3 = 1.f/(z3+1e-16f);
    size_t base = (size_t)warp * 512 + 4 * lane;
    *(float4*)&g_agg[base]       = make_float4(va0.x*i0, va0.y*i0, va0.z*i0, va0.w*i0);
    *(float4*)&g_agg[base + 128] = make_float4(va1.x*i1, va1.y*i1, va1.z*i1, va1.w*i1);
    *(float4*)&g_agg[base + 256] = make_float4(va2.x*i2, va2.y*i2, va2.z*i2, va2.w*i2);
    *(float4*)&g_agg[base + 384] = make_float4(va3.x*i3, va3.y*i3, va3.z*i3, va3.w*i3);
}

// ---------------- host entry ----------------
extern "C" void kernel_launch(void* const* d_in, const int* in_sizes, int n_in,
                              void* d_out, int out_size)
{
    const float* x   = (const float*)d_in[0];
    const void*  ei  = d_in[1];
    const float* W1  = (const float*)d_in[2];
    const float* as1 = (const float*)d_in[3];
    const float* ad1 = (const float*)d_in[4];
    const float* b1  = (const float*)d_in[5];
    const float* W2  = (const float*)d_in[6];
    const float* as2 = (const float*)d_in[7];
    const float* ad2 = (const float*)d_in[8];
    const float* b2  = (const float*)d_in[9];
    const float* W3  = (const float*)d_in[10];
    const float* as3 = (const float*)d_in[11];
    const float* ad3 = (const float*)d_in[12];
    const float* b3  = (const float*)d_in[13];

    int N = in_sizes[0] / 128;
    int E = in_sizes[1] / 2;

    int nb = (N + 1023) / 1024;
    int nsamp = (2 * E < 8192) ? 2 * E : 8192;

    // CSR build + score-vector precompute
    k_init<<<nb, 1024>>>((const int*)ei, nsamp, N);
    k_hist<<<(E + 255) / 256, 256>>>(ei, E, N);
    dim3 wgrid(4, 3);
    k_wvec_all<<<wgrid, 256>>>(W1, as1, ad1, W2, as2, ad2, W3, as3, ad3);
    k_scan1<<<nb, 1024>>>(N);
    k_scan2<<<1, 1024>>>(nb);
    k_scan3<<<nb, 1024>>>(N);
    k_scatter<<<(E + N + 255) / 256, 256>>>(ei, E, N);

    int gemmBlocks = (N + 127) / 128;
    int aggBlocks  = (N + 7) / 8;   // 8 warps (nodes) per 256-thread block

    // layer 1: exact fp32 scores (buf A); tf32 GEMM; agg -> x1 + L2 scores (buf B)
    k_scores1<<<aggBlocks, 256>>>(x, N);
    k_mma<128, 0, 0><<<gemmBlocks, 256>>>(x, W1, nullptr, nullptr, N);
    k_agg<1><<<aggBlocks, 256>>>(x, b1, N);

    // layer 2: agg -> x2 + L3 scores (buf A)
    k_mma<128, 0, 1><<<gemmBlocks, 256>>>(nullptr, W2, nullptr, nullptr, N);
    k_agg<2><<<aggBlocks, 256>>>(nullptr, b2, N);

    // layer 3 (never materializes h3 = [N,4,128])
    k_agg3<<<aggBlocks, 256>>>(N);
    k_mma<512, 1, 2><<<gemmBlocks, 256>>>(nullptr, W3, (float*)d_out, b3, N);
}